// round 14
// baseline (speedup 1.0000x reference)
#include <cuda_runtime.h>
#include <math.h>

#define HWD 512
#define HW2 (512*512)
#define NB 4
#define NCB 8
#define KS 41
#define KH 20

// ---------------- device scratch ----------------
__device__ float  d_u[NCB*KS];
__device__ double g_acc[3];              // [0]=spec num, [1]=spec mask sum, [2]=struct sum

__device__ float d_tmp_spec[NB*NCB*HWD*128];
__device__ float d_panrow [NB*HW2];
__device__ float d_panf   [NB*HW2];
__device__ float d_da_pan [NB*HW2];
__device__ float d_db_ms  [NB*NCB*HW2];
__device__ float d_saa_t  [NB*HW2];
__device__ float d_da_out [NB*NCB*HW2];
__device__ float d_db_pan [NB*HW2];
__device__ float d_sbb_x  [NB*HW2];

// ---------------- init ----------------
__global__ void k_init(const float* __restrict__ mtf) {
    int t = threadIdx.x;
    if (t < NCB*KS) {
        int c = t / KS, i = t - c*KS;
        d_u[t] = sqrtf(mtf[(size_t)c*KS*KS + i*KS + i]);  // k = u u^T
    }
    if (t == 0) { g_acc[0] = 0.0; g_acc[1] = 0.0; g_acc[2] = 0.0; }
}

// ================= device bodies (bit-identical math to the passing R4 kernels) =================

__device__ __forceinline__ void pan_row_body(const float* __restrict__ inp, int bid, int tid) {
    int idx = bid*256 + tid;   // NB*512*128
    int jg = idx & 127;
    int i  = (idx >> 7) & 511;
    int b  =  idx >> 16;
    int j0 = 4*jg;
    const float* row = inp + ((size_t)(b*9 + 8)*HWD + i)*HWD;
    const float* u = d_u;
    float o0=0.f, o1=0.f, o2=0.f, o3=0.f;
    if (j0 >= KH && j0 + 3 + KH < HWD) {
        const float* rp = row + j0 - KH;
        float rb[44];
        #pragma unroll
        for (int t = 0; t < 11; t++) {
            float4 v = ((const float4*)rp)[t];
            rb[4*t] = v.x; rb[4*t+1] = v.y; rb[4*t+2] = v.z; rb[4*t+3] = v.w;
        }
        #pragma unroll
        for (int t = 0; t < KS; t++) {
            float ut = u[t];
            o0 += ut*rb[t];   o1 += ut*rb[t+1];
            o2 += ut*rb[t+2]; o3 += ut*rb[t+3];
        }
    } else {
        #pragma unroll
        for (int m = 0; m < 4; m++) {
            int j = j0 + m;
            float s = 0.f;
            #pragma unroll
            for (int t = 0; t < KS; t++) {
                int jj = j - KH + t;
                jj = jj < 0 ? 0 : (jj > HWD-1 ? HWD-1 : jj);
                s += u[t] * row[jj];
            }
            if (m == 0) o0 = s; else if (m == 1) o1 = s; else if (m == 2) o2 = s; else o3 = s;
        }
    }
    float4* op = (float4*)(d_panrow + ((size_t)b*HWD + i)*HWD + j0);
    *op = make_float4(o0, o1, o2, o3);
}

__device__ __forceinline__ void spec_h_body(const float* __restrict__ outputs, int bid, int tid) {
    int idx = bid*256 + tid;   // NB*NCB*512*32
    int g  = idx & 31;
    int i  = (idx >> 5) & 511;
    int c  = (idx >> 14) & 7;
    int b  =  idx >> 17;
    const float* row = outputs + ((size_t)(b*NCB + c)*HWD + i)*HWD;
    const float* u = d_u + c*KS;
    float o0=0.f, o1=0.f, o2=0.f, o3=0.f;
    if (g >= 2 && g <= 29) {
        const float* rp = row + 16*g - 18;
        float rb[53];
        #pragma unroll
        for (int t = 0; t < 53; t++) rb[t] = rp[t];
        #pragma unroll
        for (int t = 0; t < KS; t++) {
            float ut = u[t];
            o0 += ut*rb[t];   o1 += ut*rb[t+4];
            o2 += ut*rb[t+8]; o3 += ut*rb[t+12];
        }
    } else {
        #pragma unroll
        for (int m = 0; m < 4; m++) {
            int j = 2 + 16*g + 4*m;
            float s = 0.f;
            #pragma unroll
            for (int t = 0; t < KS; t++) {
                int jj = j - KH + t;
                if (jj >= 0 && jj < HWD) s += u[t] * row[jj];
            }
            if (m == 0) o0 = s; else if (m == 1) o1 = s; else if (m == 2) o2 = s; else o3 = s;
        }
    }
    float4* op = (float4*)(d_tmp_spec + ((size_t)(b*NCB + c)*HWD + i)*128 + 4*g);
    *op = make_float4(o0, o1, o2, o3);
}

__device__ __forceinline__ void pan_col_body(int bid, int tid) {
    int idx = bid*256 + tid;   // NB*128*512
    int j  = idx & 511;
    int ig = (idx >> 9) & 127;
    int b  =  idx >> 16;
    int i0 = 4*ig;
    const float* u = d_u;
    const float* col = d_panrow + (size_t)b*HW2 + j;
    float o[4] = {0.f, 0.f, 0.f, 0.f};
    if (i0 >= KH && i0 + 3 + KH < HWD) {
        const float* cp = col + (size_t)(i0 - KH)*HWD;
        float rb[44];
        #pragma unroll
        for (int t = 0; t < 44; t++) rb[t] = cp[(size_t)t*HWD];
        #pragma unroll
        for (int t = 0; t < KS; t++) {
            float ut = u[t];
            o[0] += ut*rb[t];   o[1] += ut*rb[t+1];
            o[2] += ut*rb[t+2]; o[3] += ut*rb[t+3];
        }
    } else {
        #pragma unroll
        for (int m = 0; m < 4; m++) {
            int i = i0 + m;
            float s = 0.f;
            #pragma unroll
            for (int t = 0; t < KS; t++) {
                int ii = i - KH + t;
                ii = ii < 0 ? 0 : (ii > HWD-1 ? HWD-1 : ii);
                s += u[t] * col[(size_t)ii*HWD];
            }
            o[m] = s;
        }
    }
    float* op = d_panf + ((size_t)b*HWD + i0)*HWD + j;
    #pragma unroll
    for (int m = 0; m < 4; m++) op[(size_t)m*HWD] = o[m];
}

__device__ __forceinline__ void spec_v_body(const float* __restrict__ labels,
                                            const float* __restrict__ mask,
                                            int bid, int tid, double* sd) {
    int idx = bid*256 + tid;   // NB*NCB*32*128
    double num = 0.0, den = 0.0;
    {
        int bb = idx & 127;
        int g  = (idx >> 7) & 31;
        int c  = (idx >> 12) & 7;
        int b  =  idx >> 15;
        int j = 2 + 4*bb;
        const float* u = d_u + c*KS;
        const float* col = d_tmp_spec + (size_t)(b*NCB + c)*HWD*128 + bb;
        float x[4] = {0.f, 0.f, 0.f, 0.f};
        if (g >= 2 && g <= 29) {
            const float* cp = col + (size_t)(16*g - 18)*128;
            float rb[53];
            #pragma unroll
            for (int t = 0; t < 53; t++) rb[t] = cp[(size_t)t*128];
            #pragma unroll
            for (int t = 0; t < KS; t++) {
                float ut = u[t];
                x[0] += ut*rb[t];   x[1] += ut*rb[t+4];
                x[2] += ut*rb[t+8]; x[3] += ut*rb[t+12];
            }
        } else {
            #pragma unroll
            for (int m = 0; m < 4; m++) {
                int i = 2 + 16*g + 4*m;
                float s = 0.f;
                #pragma unroll
                for (int t = 0; t < KS; t++) {
                    int ii = i - KH + t;
                    if (ii >= 0 && ii < HWD) s += u[t] * col[(size_t)ii*128];
                }
                x[m] = s;
            }
        }
        #pragma unroll
        for (int m = 0; m < 4; m++) {
            int i = 2 + 16*g + 4*m;
            float y  = labels[((size_t)(b*9 + c)*HWD + i)*HWD + j];
            float mm = mask[((size_t)c*HWD + i)*HWD + j];
            num += (double)(mm * fabsf(x[m] - y));
            den += (double)mm;
        }
    }
    sd[tid] = num; __syncthreads();
    for (int s = 128; s > 0; s >>= 1) { if (tid < s) sd[tid] += sd[tid+s]; __syncthreads(); }
    double rnum = sd[0]; __syncthreads();
    sd[tid] = den; __syncthreads();
    for (int s = 128; s > 0; s >>= 1) { if (tid < s) sd[tid] += sd[tid+s]; __syncthreads(); }
    if (tid == 0) { atomicAdd(&g_acc[0], rnum); atomicAdd(&g_acc[1], sd[0]); }
}

template<int W>
__device__ __forceinline__ void boxdb_body(float* __restrict__ out, const float* __restrict__ in,
                                           int inC, int chanOff, int nC, int bid,
                                           int tx, int ty, float* sm) {
    constexpr int TS = 31 + 2*W;
    float* raw = sm;                 // TS*(TS+1)
    float* hs  = sm + TS*(TS+1);     // TS*32
    int p  = bid >> 8;
    int by = (bid >> 4) & 15;
    int bx =  bid & 15;
    int b = p / nC, c = p - b*nC;
    const float* ip = in + (size_t)(b*inC + chanOff + c)*HW2;
    float* op = out + (size_t)p*HW2;
    int y0 = by*32, x0 = bx*32;
    int ty0 = y0 - (W-1), tx0 = x0 - (W-1);
    int tid = ty*32 + tx;
    for (int idx = tid; idx < TS*TS; idx += 256) {
        int r = idx / TS, q = idx - r*TS;
        int gi = ty0 + r, gj = tx0 + q;
        raw[r*(TS+1)+q] = ((unsigned)gi < HWD && (unsigned)gj < HWD) ? ip[gi*HWD + gj] : 0.f;
    }
    __syncthreads();
    for (int r = ty; r < TS; r += 8) {
        float s = 0.f;
        #pragma unroll
        for (int q = 0; q < 2*W; q++) s += raw[r*(TS+1) + tx + q];
        hs[r*32 + tx] = s;
    }
    __syncthreads();
    const float invn = 1.0f / (4.0f*W*W);
    int ly0 = ty*4;
    float s = 0.f;
    #pragma unroll
    for (int r = 0; r < 2*W; r++) s += hs[(ly0 + r)*32 + tx];
    #pragma unroll
    for (int k = 0; k < 4; k++) {
        int ly = ly0 + k;
        op[(y0 + ly)*HWD + x0 + tx] = raw[(ly + W - 1)*(TS+1) + tx + W - 1] - s*invn;
        if (k < 3) s += hs[(ly + 2*W)*32 + tx] - hs[ly*32 + tx];
    }
}

template<int W>
__device__ __forceinline__ void boxsq_body(float* __restrict__ out, const float* __restrict__ A,
                                           int bid, int tx, int ty, float* sm) {
    constexpr int TS = 31 + 2*W;
    float* raw = sm;
    float* hs  = sm + TS*(TS+1);
    int b  = bid >> 8;
    int by = (bid >> 4) & 15;
    int bx =  bid & 15;
    const float* ap = A + (size_t)b*HW2;
    float* op = out + (size_t)b*HW2;
    int y0 = by*32, x0 = bx*32;
    int ty0 = y0 - (W-1), tx0 = x0 - (W-1);
    int tid = ty*32 + tx;
    for (int idx = tid; idx < TS*TS; idx += 256) {
        int r = idx / TS, q = idx - r*TS;
        int gi = ty0 + r, gj = tx0 + q;
        float v = 0.f;
        if ((unsigned)gi < HWD && (unsigned)gj < HWD) { float a = ap[gi*HWD + gj]; v = a*a; }
        raw[r*(TS+1)+q] = v;
    }
    __syncthreads();
    for (int r = ty; r < TS; r += 8) {
        float s = 0.f;
        #pragma unroll
        for (int q = 0; q < 2*W; q++) s += raw[r*(TS+1) + tx + q];
        hs[r*32 + tx] = s;
    }
    __syncthreads();
    int ly0 = ty*4;
    float s = 0.f;
    #pragma unroll
    for (int r = 0; r < 2*W; r++) s += hs[(ly0 + r)*32 + tx];
    #pragma unroll
    for (int k = 0; k < 4; k++) {
        int ly = ly0 + k;
        op[(y0 + ly)*HWD + x0 + tx] = s;
        if (k < 3) s += hs[(ly + 2*W)*32 + tx] - hs[ly*32 + tx];
    }
}

// ================= stage dispatcher kernels =================

// Stage A: pan_row | spec_h | boxdb8(db_ms) | boxdb2(da_out) | boxdb2(db_pan)
__global__ void k_stageA(const float* __restrict__ inp, const float* __restrict__ outputs,
                         const float* __restrict__ labels) {
    __shared__ __align__(16) float sm[3760];
    int bid = blockIdx.x;
    int tx = threadIdx.x, ty = threadIdx.y;
    int tid = ty*32 + tx;
    if (bid < 1024) {
        pan_row_body(inp, bid, tid);
    } else if (bid < 3072) {
        spec_h_body(outputs, bid - 1024, tid);
    } else if (bid < 11264) {
        boxdb_body<8>(d_db_ms, inp, 9, 0, NCB, bid - 3072, tx, ty, sm);
    } else if (bid < 19456) {
        boxdb_body<2>(d_da_out, outputs, NCB, 0, NCB, bid - 11264, tx, ty, sm);
    } else {
        boxdb_body<2>(d_db_pan, labels, 9, 8, 1, bid - 19456, tx, ty, sm);
    }
}

// Stage B: pan_col | spec_v | boxsq2(sbb_x)
__global__ void k_stageB(const float* __restrict__ labels, const float* __restrict__ mask) {
    __shared__ __align__(16) float sm[2380];
    int bid = blockIdx.x;
    int tx = threadIdx.x, ty = threadIdx.y;
    int tid = ty*32 + tx;
    if (bid < 1024) {
        pan_col_body(bid, tid);
    } else if (bid < 1536) {
        spec_v_body(labels, mask, bid - 1024, tid, (double*)sm);
    } else {
        boxsq_body<2>(d_sbb_x, d_db_pan, bid - 1536, tx, ty, sm);
    }
}

// Stage C: boxdb8(da_pan)   Stage D: boxsq8(saa_t)
__global__ void k_stageC() {
    __shared__ __align__(16) float sm[3760];
    boxdb_body<8>(d_da_pan, d_panf, 1, 0, 1, blockIdx.x, threadIdx.x, threadIdx.y, sm);
}
__global__ void k_stageD() {
    __shared__ __align__(16) float sm[3760];
    boxsq_body<8>(d_saa_t, d_da_pan, blockIdx.x, threadIdx.x, threadIdx.y, sm);
}

// ---------------- mega-fused structural kernel (unchanged from R4) ----------------
__global__ void k_fuse() {
    __shared__ float sm[7520];
    __shared__ double sd[256];
    int p = blockIdx.z;
    int b = p >> 3;
    int tx = threadIdx.x, ty = threadIdx.y;
    int tid = ty*32 + tx;
    int y0 = blockIdx.y*32, x0 = blockIdx.x*32;
    int ly0 = ty*4;

    // ---- phase 1: w=8 (thr) ----
    {
        float* rawA = sm;              // [47][48]
        float* rawB = sm + 2256;       // [47][48]
        float* hsAB = sm + 4512;       // [47][32]
        float* hsBB = sm + 6016;       // [47][32]
        const float* A = d_da_pan + (size_t)b*HW2;
        const float* B = d_db_ms  + (size_t)p*HW2;
        int ty0 = y0 - 7, tx0 = x0 - 7;
        for (int idx = tid; idx < 47*47; idx += 256) {
            int r = idx / 47, q = idx - r*47;
            int gi = ty0 + r, gj = tx0 + q;
            float va = 0.f, vb = 0.f;
            if ((unsigned)gi < HWD && (unsigned)gj < HWD) {
                int o = gi*HWD + gj;
                va = A[o]; vb = B[o];
            }
            rawA[r*48 + q] = va; rawB[r*48 + q] = vb;
        }
        __syncthreads();
        for (int r = ty; r < 47; r += 8) {
            float sa = 0.f, sb = 0.f;
            #pragma unroll
            for (int q = 0; q < 16; q++) {
                float a = rawA[r*48 + tx + q], bb = rawB[r*48 + tx + q];
                sa += a*bb; sb += bb*bb;
            }
            hsAB[r*32 + tx] = sa; hsBB[r*32 + tx] = sb;
        }
        __syncthreads();
    }
    float thrv[4];
    {
        float* hsAB = sm + 4512;
        float* hsBB = sm + 6016;
        const float* SAA = d_saa_t + (size_t)b*HW2;
        float sab = 0.f, sbb = 0.f;
        #pragma unroll
        for (int r = 0; r < 16; r++) { sab += hsAB[(ly0+r)*32 + tx]; sbb += hsBB[(ly0+r)*32 + tx]; }
        #pragma unroll
        for (int k = 0; k < 4; k++) {
            int oi = y0 + ly0 + k;
            float saa = SAA[oi*HWD + x0 + tx];
            thrv[k] = 1.f - sab / (sqrtf(saa*sbb) + 1e-20f);
            if (k < 3) {
                sab += hsAB[(ly0+16+k)*32 + tx] - hsAB[(ly0+k)*32 + tx];
                sbb += hsBB[(ly0+16+k)*32 + tx] - hsBB[(ly0+k)*32 + tx];
            }
        }
    }
    __syncthreads();

    // ---- phase 2: w=2 (X) ----
    {
        float* rawC = sm;              // [35][36]
        float* rawD = sm + 1260;       // [35][36]
        const float* C = d_da_out + (size_t)p*HW2;
        const float* D = d_db_pan + (size_t)b*HW2;
        int ty0 = y0 - 1, tx0 = x0 - 1;
        for (int idx = tid; idx < 35*35; idx += 256) {
            int r = idx / 35, q = idx - r*35;
            int gi = ty0 + r, gj = tx0 + q;
            float vc = 0.f, vd = 0.f;
            if ((unsigned)gi < HWD && (unsigned)gj < HWD) {
                int o = gi*HWD + gj;
                vc = C[o]; vd = D[o];
            }
            rawC[r*36 + q] = vc; rawD[r*36 + q] = vd;
        }
        __syncthreads();
        float* hsCD = sm + 2520;       // [35][32]
        float* hsCC = sm + 3640;       // [35][32]
        for (int r = ty; r < 35; r += 8) {
            float scd = 0.f, scc = 0.f;
            #pragma unroll
            for (int q = 0; q < 4; q++) {
                float cc = rawC[r*36 + tx + q], dd = rawD[r*36 + tx + q];
                scd += cc*dd; scc += cc*cc;
            }
            hsCD[r*32 + tx] = scd; hsCC[r*32 + tx] = scc;
        }
        __syncthreads();
        const float* SBB = d_sbb_x + (size_t)b*HW2;
        float scd = 0.f, scc = 0.f;
        #pragma unroll
        for (int r = 0; r < 4; r++) { scd += hsCD[(ly0+r)*32 + tx]; scc += hsCC[(ly0+r)*32 + tx]; }
        double acc = 0.0;
        #pragma unroll
        for (int k = 0; k < 4; k++) {
            int oi = y0 + ly0 + k;
            float sbbx = SBB[oi*HWD + x0 + tx];
            float xc = scd / (sqrtf(scc*sbbx) + 1e-20f);
            xc = fmaxf(xc, -1.f);
            float X = 1.f - xc;
            if (X > thrv[k]) acc += (double)X;
            if (k < 3) {
                scd += hsCD[(ly0+4+k)*32 + tx] - hsCD[(ly0+k)*32 + tx];
                scc += hsCC[(ly0+4+k)*32 + tx] - hsCC[(ly0+k)*32 + tx];
            }
        }
        sd[tid] = acc;
    }
    __syncthreads();
    for (int s = 128; s > 0; s >>= 1) { if (tid < s) sd[tid] += sd[tid+s]; __syncthreads(); }
    if (tid == 0) atomicAdd(&g_acc[2], sd[0]);
}

__global__ void k_write(float* __restrict__ out) {
    double l_spec   = g_acc[0] / g_acc[1];
    double l_struct = g_acc[2] / (double)((size_t)NB*NCB*HW2);
    out[0] = (float)(l_spec + 0.25 * l_struct);
}

// ---------------- host launcher (single stream, 7 launches) ----------------
extern "C" void kernel_launch(void* const* d_in, const int* in_sizes, int n_in,
                              void* d_out, int out_size) {
    const float* outputs = (const float*)d_in[0];
    const float* labels  = (const float*)d_in[1];
    const float* inp     = (const float*)d_in[2];
    const float* mtf     = (const float*)d_in[3];
    const float* mask    = (const float*)d_in[4];
    float* out = (float*)d_out;

    dim3 bt(32, 8);

    k_init<<<1, 512>>>(mtf);
    k_stageA<<<20480, bt>>>(inp, outputs, labels);
    k_stageB<<<2560, bt>>>(labels, mask);
    k_stageC<<<1024, bt>>>();
    k_stageD<<<1024, bt>>>();
    k_fuse<<<dim3(16,16,NB*NCB), bt>>>();
    k_write<<<1, 1>>>(out);
}

// round 15
// speedup vs baseline: 1.2620x; 1.2620x over previous
#include <cuda_runtime.h>
#include <math.h>

#define HWD 512
#define HW2 (512*512)
#define NB 4
#define NCB 8
#define KS 41
#define KH 20

// ---------------- device scratch ----------------
__device__ float  d_u[NCB*KS];
__device__ double g_acc[3];              // [0]=spec num, [1]=spec mask sum, [2]=struct sum

__device__ float d_tmp_spec[NB*NCB*HWD*128];
__device__ float d_panrow [NB*HW2];
__device__ float d_panf   [NB*HW2];
__device__ float d_da_pan [NB*HW2];
__device__ float d_db_ms  [NB*NCB*HW2];
__device__ float d_saa_t  [NB*HW2];
__device__ float d_da_out [NB*NCB*HW2];
__device__ float d_db_pan [NB*HW2];

// ---------------- init ----------------
__global__ void k_init(const float* __restrict__ mtf) {
    int t = threadIdx.x;
    if (t < NCB*KS) {
        int c = t / KS, i = t - c*KS;
        d_u[t] = sqrtf(mtf[(size_t)c*KS*KS + i*KS + i]);  // k = u u^T
    }
    if (t == 0) { g_acc[0] = 0.0; g_acc[1] = 0.0; g_acc[2] = 0.0; }
}

// ================= device bodies (identical math to the 338us R4 kernels) =================

__device__ __forceinline__ void pan_row_body(const float* __restrict__ inp, int bid, int tid) {
    int idx = bid*256 + tid;   // NB*512*128
    int jg = idx & 127;
    int i  = (idx >> 7) & 511;
    int b  =  idx >> 16;
    int j0 = 4*jg;
    const float* row = inp + ((size_t)(b*9 + 8)*HWD + i)*HWD;
    const float* u = d_u;
    float o0=0.f, o1=0.f, o2=0.f, o3=0.f;
    if (j0 >= KH && j0 + 3 + KH < HWD) {
        const float* rp = row + j0 - KH;
        float rb[44];
        #pragma unroll
        for (int t = 0; t < 11; t++) {
            float4 v = ((const float4*)rp)[t];
            rb[4*t] = v.x; rb[4*t+1] = v.y; rb[4*t+2] = v.z; rb[4*t+3] = v.w;
        }
        #pragma unroll
        for (int t = 0; t < KS; t++) {
            float ut = u[t];
            o0 += ut*rb[t];   o1 += ut*rb[t+1];
            o2 += ut*rb[t+2]; o3 += ut*rb[t+3];
        }
    } else {
        #pragma unroll
        for (int m = 0; m < 4; m++) {
            int j = j0 + m;
            float s = 0.f;
            #pragma unroll
            for (int t = 0; t < KS; t++) {
                int jj = j - KH + t;
                jj = jj < 0 ? 0 : (jj > HWD-1 ? HWD-1 : jj);
                s += u[t] * row[jj];
            }
            if (m == 0) o0 = s; else if (m == 1) o1 = s; else if (m == 2) o2 = s; else o3 = s;
        }
    }
    float4* op = (float4*)(d_panrow + ((size_t)b*HWD + i)*HWD + j0);
    *op = make_float4(o0, o1, o2, o3);
}

__device__ __forceinline__ void spec_h_body(const float* __restrict__ outputs, int bid, int tid) {
    int idx = bid*256 + tid;   // NB*NCB*512*32
    int g  = idx & 31;
    int i  = (idx >> 5) & 511;
    int c  = (idx >> 14) & 7;
    int b  =  idx >> 17;
    const float* row = outputs + ((size_t)(b*NCB + c)*HWD + i)*HWD;
    const float* u = d_u + c*KS;
    float o0=0.f, o1=0.f, o2=0.f, o3=0.f;
    if (g >= 2 && g <= 29) {
        const float* rp = row + 16*g - 18;
        float rb[53];
        #pragma unroll
        for (int t = 0; t < 53; t++) rb[t] = rp[t];
        #pragma unroll
        for (int t = 0; t < KS; t++) {
            float ut = u[t];
            o0 += ut*rb[t];   o1 += ut*rb[t+4];
            o2 += ut*rb[t+8]; o3 += ut*rb[t+12];
        }
    } else {
        #pragma unroll
        for (int m = 0; m < 4; m++) {
            int j = 2 + 16*g + 4*m;
            float s = 0.f;
            #pragma unroll
            for (int t = 0; t < KS; t++) {
                int jj = j - KH + t;
                if (jj >= 0 && jj < HWD) s += u[t] * row[jj];
            }
            if (m == 0) o0 = s; else if (m == 1) o1 = s; else if (m == 2) o2 = s; else o3 = s;
        }
    }
    float4* op = (float4*)(d_tmp_spec + ((size_t)(b*NCB + c)*HWD + i)*128 + 4*g);
    *op = make_float4(o0, o1, o2, o3);
}

__device__ __forceinline__ void pan_col_body(int bid, int tid) {
    int idx = bid*256 + tid;   // NB*128*512
    int j  = idx & 511;
    int ig = (idx >> 9) & 127;
    int b  =  idx >> 16;
    int i0 = 4*ig;
    const float* u = d_u;
    const float* col = d_panrow + (size_t)b*HW2 + j;
    float o[4] = {0.f, 0.f, 0.f, 0.f};
    if (i0 >= KH && i0 + 3 + KH < HWD) {
        const float* cp = col + (size_t)(i0 - KH)*HWD;
        float rb[44];
        #pragma unroll
        for (int t = 0; t < 44; t++) rb[t] = cp[(size_t)t*HWD];
        #pragma unroll
        for (int t = 0; t < KS; t++) {
            float ut = u[t];
            o[0] += ut*rb[t];   o[1] += ut*rb[t+1];
            o[2] += ut*rb[t+2]; o[3] += ut*rb[t+3];
        }
    } else {
        #pragma unroll
        for (int m = 0; m < 4; m++) {
            int i = i0 + m;
            float s = 0.f;
            #pragma unroll
            for (int t = 0; t < KS; t++) {
                int ii = i - KH + t;
                ii = ii < 0 ? 0 : (ii > HWD-1 ? HWD-1 : ii);
                s += u[t] * col[(size_t)ii*HWD];
            }
            o[m] = s;
        }
    }
    float* op = d_panf + ((size_t)b*HWD + i0)*HWD + j;
    #pragma unroll
    for (int m = 0; m < 4; m++) op[(size_t)m*HWD] = o[m];
}

__device__ __forceinline__ void spec_v_body(const float* __restrict__ labels,
                                            const float* __restrict__ mask,
                                            int bid, int tid, double* sd) {
    int idx = bid*256 + tid;   // NB*NCB*32*128
    double num = 0.0, den = 0.0;
    {
        int bb = idx & 127;
        int g  = (idx >> 7) & 31;
        int c  = (idx >> 12) & 7;
        int b  =  idx >> 15;
        int j = 2 + 4*bb;
        const float* u = d_u + c*KS;
        const float* col = d_tmp_spec + (size_t)(b*NCB + c)*HWD*128 + bb;
        float x[4] = {0.f, 0.f, 0.f, 0.f};
        if (g >= 2 && g <= 29) {
            const float* cp = col + (size_t)(16*g - 18)*128;
            float rb[53];
            #pragma unroll
            for (int t = 0; t < 53; t++) rb[t] = cp[(size_t)t*128];
            #pragma unroll
            for (int t = 0; t < KS; t++) {
                float ut = u[t];
                x[0] += ut*rb[t];   x[1] += ut*rb[t+4];
                x[2] += ut*rb[t+8]; x[3] += ut*rb[t+12];
            }
        } else {
            #pragma unroll
            for (int m = 0; m < 4; m++) {
                int i = 2 + 16*g + 4*m;
                float s = 0.f;
                #pragma unroll
                for (int t = 0; t < KS; t++) {
                    int ii = i - KH + t;
                    if (ii >= 0 && ii < HWD) s += u[t] * col[(size_t)ii*128];
                }
                x[m] = s;
            }
        }
        #pragma unroll
        for (int m = 0; m < 4; m++) {
            int i = 2 + 16*g + 4*m;
            float y  = labels[((size_t)(b*9 + c)*HWD + i)*HWD + j];
            float mm = mask[((size_t)c*HWD + i)*HWD + j];
            num += (double)(mm * fabsf(x[m] - y));
            den += (double)mm;
        }
    }
    sd[tid] = num; __syncthreads();
    for (int s = 128; s > 0; s >>= 1) { if (tid < s) sd[tid] += sd[tid+s]; __syncthreads(); }
    double rnum = sd[0]; __syncthreads();
    sd[tid] = den; __syncthreads();
    for (int s = 128; s > 0; s >>= 1) { if (tid < s) sd[tid] += sd[tid+s]; __syncthreads(); }
    if (tid == 0) { atomicAdd(&g_acc[0], rnum); atomicAdd(&g_acc[1], sd[0]); }
}

template<int W>
__device__ __forceinline__ void boxdb_body(float* __restrict__ out, const float* __restrict__ in,
                                           int inC, int chanOff, int nC, int bid,
                                           int tx, int ty, float* sm) {
    constexpr int TS = 31 + 2*W;
    float* raw = sm;                 // TS*(TS+1)
    float* hs  = sm + TS*(TS+1);     // TS*32
    int p  = bid >> 8;
    int by = (bid >> 4) & 15;
    int bx =  bid & 15;
    int b = p / nC, c = p - b*nC;
    const float* ip = in + (size_t)(b*inC + chanOff + c)*HW2;
    float* op = out + (size_t)p*HW2;
    int y0 = by*32, x0 = bx*32;
    int ty0 = y0 - (W-1), tx0 = x0 - (W-1);
    int tid = ty*32 + tx;
    for (int idx = tid; idx < TS*TS; idx += 256) {
        int r = idx / TS, q = idx - r*TS;
        int gi = ty0 + r, gj = tx0 + q;
        raw[r*(TS+1)+q] = ((unsigned)gi < HWD && (unsigned)gj < HWD) ? ip[gi*HWD + gj] : 0.f;
    }
    __syncthreads();
    for (int r = ty; r < TS; r += 8) {
        float s = 0.f;
        #pragma unroll
        for (int q = 0; q < 2*W; q++) s += raw[r*(TS+1) + tx + q];
        hs[r*32 + tx] = s;
    }
    __syncthreads();
    const float invn = 1.0f / (4.0f*W*W);
    int ly0 = ty*4;
    float s = 0.f;
    #pragma unroll
    for (int r = 0; r < 2*W; r++) s += hs[(ly0 + r)*32 + tx];
    #pragma unroll
    for (int k = 0; k < 4; k++) {
        int ly = ly0 + k;
        op[(y0 + ly)*HWD + x0 + tx] = raw[(ly + W - 1)*(TS+1) + tx + W - 1] - s*invn;
        if (k < 3) s += hs[(ly + 2*W)*32 + tx] - hs[ly*32 + tx];
    }
}

// ================= merged kernels (homogeneous register classes) =================

// conv class A: pan_row | spec_h   (cap regs; spec_h may spill a little)
__global__ void __launch_bounds__(256, 4) k_convA(const float* __restrict__ inp,
                                                  const float* __restrict__ outputs) {
    int bid = blockIdx.x, tid = threadIdx.x;
    if (bid < 1024) pan_row_body(inp, bid, tid);
    else            spec_h_body(outputs, bid - 1024, tid);
}

// conv class B: pan_col | spec_v
__global__ void __launch_bounds__(256, 4) k_convB(const float* __restrict__ labels,
                                                  const float* __restrict__ mask) {
    __shared__ double sd[256];
    int bid = blockIdx.x, tid = threadIdx.x;
    if (bid < 1024) pan_col_body(bid, tid);
    else            spec_v_body(labels, mask, bid - 1024, tid, sd);
}

// box class: boxdb8(db_ms) | boxdb2(da_out) | boxdb2(db_pan)  (all ~28 regs)
__global__ void k_box1(const float* __restrict__ inp, const float* __restrict__ outputs,
                       const float* __restrict__ labels) {
    __shared__ __align__(16) float sm[3760];
    int bid = blockIdx.x;
    int tx = threadIdx.x & 31, ty = threadIdx.x >> 5;
    if (bid < 8192)       boxdb_body<8>(d_db_ms,  inp,     9, 0, NCB, bid,         tx, ty, sm);
    else if (bid < 16384) boxdb_body<2>(d_da_out, outputs, NCB, 0, NCB, bid - 8192, tx, ty, sm);
    else                  boxdb_body<2>(d_db_pan, labels,  9, 8, 1,   bid - 16384, tx, ty, sm);
}

// standalone: da_pan (needs panf) and saa_t (needs da_pan)
__global__ void k_box2() {
    __shared__ __align__(16) float sm[3760];
    boxdb_body<8>(d_da_pan, d_panf, 1, 0, 1, blockIdx.x, threadIdx.x & 31, threadIdx.x >> 5, sm);
}

__global__ void k_box3() {   // boxsq8: saa_t = box16(da_pan^2)
    constexpr int TS = 47;
    __shared__ __align__(16) float raw[TS][TS+1];
    __shared__ float hs[TS][32];
    int bid = blockIdx.x;
    int tx = threadIdx.x & 31, ty = threadIdx.x >> 5;
    int b  = bid >> 8, by = (bid >> 4) & 15, bx = bid & 15;
    const float* ap = d_da_pan + (size_t)b*HW2;
    float* op = d_saa_t + (size_t)b*HW2;
    int y0 = by*32, x0 = bx*32;
    int ty0 = y0 - 7, tx0 = x0 - 7;
    int tid = threadIdx.x;
    for (int idx = tid; idx < TS*TS; idx += 256) {
        int r = idx / TS, q = idx - r*TS;
        int gi = ty0 + r, gj = tx0 + q;
        float v = 0.f;
        if ((unsigned)gi < HWD && (unsigned)gj < HWD) { float a = ap[gi*HWD + gj]; v = a*a; }
        raw[r][q] = v;
    }
    __syncthreads();
    for (int r = ty; r < TS; r += 8) {
        float s = 0.f;
        #pragma unroll
        for (int q = 0; q < 16; q++) s += raw[r][tx + q];
        hs[r][tx] = s;
    }
    __syncthreads();
    int ly0 = ty*4;
    float s = 0.f;
    #pragma unroll
    for (int r = 0; r < 16; r++) s += hs[ly0 + r][tx];
    #pragma unroll
    for (int k = 0; k < 4; k++) {
        int ly = ly0 + k;
        op[(y0 + ly)*HWD + x0 + tx] = s;
        if (k < 3) s += hs[ly + 16][tx] - hs[ly][tx];
    }
}

// ---------------- mega-fused structural kernel ----------------
// phase 1: two-level (4+4) horizontal product sums; phase 2: sbb computed in-tile.
__global__ void k_fuse() {
    __shared__ __align__(16) float sm[8648];
    __shared__ double sd[256];
    int p = blockIdx.z;
    int b = p >> 3;
    int tx = threadIdx.x, ty = threadIdx.y;
    int tid = ty*32 + tx;
    int y0 = blockIdx.y*32, x0 = blockIdx.x*32;
    int ly0 = ty*4;

    // ---- phase 1: w=8 (thr) ----
    {
        float* rawA = sm;              // 47*48 = 2256  (da_pan)
        float* rawB = sm + 2256;       // 2256          (db_ms)
        float* s4AB = sm + 4512;       // 47*44 = 2068
        float* s4BB = sm + 6580;       // 2068
        const float* A = d_da_pan + (size_t)b*HW2;
        const float* B = d_db_ms  + (size_t)p*HW2;
        int ty0 = y0 - 7, tx0 = x0 - 7;
        for (int idx = tid; idx < 47*47; idx += 256) {
            int r = idx / 47, q = idx - r*47;
            int gi = ty0 + r, gj = tx0 + q;
            float va = 0.f, vb = 0.f;
            if ((unsigned)gi < HWD && (unsigned)gj < HWD) {
                int o = gi*HWD + gj;
                va = A[o]; vb = B[o];
            }
            rawA[r*48 + q] = va; rawB[r*48 + q] = vb;
        }
        __syncthreads();
        // level 1: 4-tap product sums at 44 offsets
        for (int idx = tid; idx < 47*44; idx += 256) {
            int r = idx / 44, q = idx - r*44;
            const float* ra = rawA + r*48 + q;
            const float* rb = rawB + r*48 + q;
            float sab = 0.f, sbb = 0.f;
            #pragma unroll
            for (int t = 0; t < 4; t++) { float a = ra[t], bb = rb[t]; sab += a*bb; sbb += bb*bb; }
            s4AB[idx] = sab; s4BB[idx] = sbb;
        }
        __syncthreads();
        // level 2: 16-tap = 4x 4-tap; overwrite raw region
        float* hsAB = sm;              // 47*32 = 1504
        float* hsBB = sm + 1504;
        for (int idx = tid; idx < 47*32; idx += 256) {
            int r = idx / 32, q = idx - r*32;
            int o = r*44 + q;
            hsAB[idx] = s4AB[o] + s4AB[o+4] + s4AB[o+8] + s4AB[o+12];
            hsBB[idx] = s4BB[o] + s4BB[o+4] + s4BB[o+8] + s4BB[o+12];
        }
        __syncthreads();
    }
    float thrv[4];
    {
        float* hsAB = sm;
        float* hsBB = sm + 1504;
        const float* SAA = d_saa_t + (size_t)b*HW2;
        float sab = 0.f, sbb = 0.f;
        #pragma unroll
        for (int r = 0; r < 16; r++) { sab += hsAB[(ly0+r)*32 + tx]; sbb += hsBB[(ly0+r)*32 + tx]; }
        #pragma unroll
        for (int k = 0; k < 4; k++) {
            int oi = y0 + ly0 + k;
            float saa = SAA[oi*HWD + x0 + tx];
            thrv[k] = 1.f - sab / (sqrtf(saa*sbb) + 1e-20f);
            if (k < 3) {
                sab += hsAB[(ly0+16+k)*32 + tx] - hsAB[(ly0+k)*32 + tx];
                sbb += hsBB[(ly0+16+k)*32 + tx] - hsBB[(ly0+k)*32 + tx];
            }
        }
    }
    __syncthreads();

    // ---- phase 2: w=2 (X), with sbb computed in-tile ----
    {
        float* rawC = sm;              // 35*36 = 1260  (da_out)
        float* rawD = sm + 1260;       // 1260          (db_pan)
        const float* C = d_da_out + (size_t)p*HW2;
        const float* D = d_db_pan + (size_t)b*HW2;
        int ty0 = y0 - 1, tx0 = x0 - 1;
        for (int idx = tid; idx < 35*35; idx += 256) {
            int r = idx / 35, q = idx - r*35;
            int gi = ty0 + r, gj = tx0 + q;
            float vc = 0.f, vd = 0.f;
            if ((unsigned)gi < HWD && (unsigned)gj < HWD) {
                int o = gi*HWD + gj;
                vc = C[o]; vd = D[o];
            }
            rawC[r*36 + q] = vc; rawD[r*36 + q] = vd;
        }
        __syncthreads();
        float* hsCD = sm + 2520;       // 35*32 = 1120
        float* hsCC = sm + 3640;
        float* hsDD = sm + 4760;
        for (int r = ty; r < 35; r += 8) {
            float scd = 0.f, scc = 0.f, sdd = 0.f;
            #pragma unroll
            for (int q = 0; q < 4; q++) {
                float cc = rawC[r*36 + tx + q], dd = rawD[r*36 + tx + q];
                scd += cc*dd; scc += cc*cc; sdd += dd*dd;
            }
            hsCD[r*32 + tx] = scd; hsCC[r*32 + tx] = scc; hsDD[r*32 + tx] = sdd;
        }
        __syncthreads();
        float scd = 0.f, scc = 0.f, sdd = 0.f;
        #pragma unroll
        for (int r = 0; r < 4; r++) {
            scd += hsCD[(ly0+r)*32 + tx];
            scc += hsCC[(ly0+r)*32 + tx];
            sdd += hsDD[(ly0+r)*32 + tx];
        }
        double acc = 0.0;
        #pragma unroll
        for (int k = 0; k < 4; k++) {
            float xc = scd / (sqrtf(scc*sdd) + 1e-20f);
            xc = fmaxf(xc, -1.f);
            float X = 1.f - xc;
            if (X > thrv[k]) acc += (double)X;
            if (k < 3) {
                scd += hsCD[(ly0+4+k)*32 + tx] - hsCD[(ly0+k)*32 + tx];
                scc += hsCC[(ly0+4+k)*32 + tx] - hsCC[(ly0+k)*32 + tx];
                sdd += hsDD[(ly0+4+k)*32 + tx] - hsDD[(ly0+k)*32 + tx];
            }
        }
        sd[tid] = acc;
    }
    __syncthreads();
    for (int s = 128; s > 0; s >>= 1) { if (tid < s) sd[tid] += sd[tid+s]; __syncthreads(); }
    if (tid == 0) atomicAdd(&g_acc[2], sd[0]);
}

__global__ void k_write(float* __restrict__ out) {
    double l_spec   = g_acc[0] / g_acc[1];
    double l_struct = g_acc[2] / (double)((size_t)NB*NCB*HW2);
    out[0] = (float)(l_spec + 0.25 * l_struct);
}

// ---------------- host launcher (single stream, 8 launches) ----------------
extern "C" void kernel_launch(void* const* d_in, const int* in_sizes, int n_in,
                              void* d_out, int out_size) {
    const float* outputs = (const float*)d_in[0];
    const float* labels  = (const float*)d_in[1];
    const float* inp     = (const float*)d_in[2];
    const float* mtf     = (const float*)d_in[3];
    const float* mask    = (const float*)d_in[4];
    float* out = (float*)d_out;

    k_init<<<1, 512>>>(mtf);
    k_convA<<<3072, 256>>>(inp, outputs);          // pan_row | spec_h
    k_box1<<<17408, 256>>>(inp, outputs, labels);  // db_ms | da_out | db_pan
    k_convB<<<1536, 256>>>(labels, mask);          // pan_col | spec_v
    k_box2<<<1024, 256>>>();                       // da_pan
    k_box3<<<1024, 256>>>();                       // saa_t
    k_fuse<<<dim3(16,16,NB*NCB), dim3(32,8)>>>();
    k_write<<<1, 1>>>(out);
}